// round 16
// baseline (speedup 1.0000x reference)
#include <cuda_runtime.h>
#include <cuda_fp16.h>
#include <cstdint>

// Problem constants
#define BB 2
#define SS 2048
#define DD 1024
#define HH 8
#define EE 128
#define KW 16
#define MM (BB*SS)          // 4096 rows
#define KK 1024             // GEMM K (both projections)

typedef __half fp16;

// ---------------------------------------------------------------------------
// Device scratch (allocation-free rule)
// ---------------------------------------------------------------------------
__device__ fp16  g_xhi[MM*KK], g_xlo[MM*KK];       // x split [4096,1024]
__device__ fp16  g_wtq[EE*HH*DD];                  // Wq^T [128 (e), 8192 (h*1024+d)]
__device__ fp16  g_wtk[EE*HH*DD];
__device__ fp16  g_wtv[EE*HH*DD];
__device__ fp16  g_wot[DD*HH*EE];                  // Wo^T [1024 (d), 1024 (he)]
__device__ float g_q[BB*HH*SS*EE];                 // [B,H,S,E]
__device__ float g_k[BB*HH*SS*EE];
__device__ float g_v[BB*HH*SS*EE];
__device__ fp16  g_attn_hi[MM*KK], g_attn_lo[MM*KK];  // [B,S,H,E] = [4096,1024]

// ---------------------------------------------------------------------------
// Helpers (sm_80-class PTX only — legal on compute_103)
// ---------------------------------------------------------------------------
__device__ __forceinline__ uint32_t smem_to_u32(const void* p) {
    uint32_t a;
    asm("{ .reg .u64 t; cvta.to.shared.u64 t, %1; cvt.u32.u64 %0, t; }" : "=r"(a) : "l"(p));
    return a;
}
__device__ __forceinline__ void cp_async16(uint32_t saddr, const void* gptr) {
    asm volatile("cp.async.cg.shared.global [%0], [%1], 16;\n" :: "r"(saddr), "l"(gptr));
}
__device__ __forceinline__ void ldsm4(uint32_t* r, uint32_t addr) {
    asm volatile("ldmatrix.sync.aligned.m8n8.x4.shared.b16 {%0,%1,%2,%3}, [%4];\n"
        : "=r"(r[0]), "=r"(r[1]), "=r"(r[2]), "=r"(r[3]) : "r"(addr));
}
__device__ __forceinline__ void ldsm2(uint32_t* r, uint32_t addr) {
    asm volatile("ldmatrix.sync.aligned.m8n8.x2.shared.b16 {%0,%1}, [%2];\n"
        : "=r"(r[0]), "=r"(r[1]) : "r"(addr));
}
__device__ __forceinline__ void mma16816(float* c, const uint32_t* a, const uint32_t* b) {
    asm volatile("mma.sync.aligned.m16n8k16.row.col.f32.f16.f16.f32 "
        "{%0,%1,%2,%3}, {%4,%5,%6,%7}, {%8,%9}, {%0,%1,%2,%3};\n"
        : "+f"(c[0]), "+f"(c[1]), "+f"(c[2]), "+f"(c[3])
        : "r"(a[0]), "r"(a[1]), "r"(a[2]), "r"(a[3]), "r"(b[0]), "r"(b[1]));
}

__device__ __forceinline__ void split_fp16(float v, fp16& hi, fp16& lo) {
    hi = __float2half_rn(v);
    lo = __float2half_rn(v - __half2float(hi));
}

// ---------------------------------------------------------------------------
// Kernel A: elementwise split-convert of x -> g_xhi/g_xlo (fp16)
// ---------------------------------------------------------------------------
__global__ __launch_bounds__(256) void convert_x_kernel(const float* __restrict__ x) {
    int t = blockIdx.x * 256 + threadIdx.x;
    size_t base = (size_t)t * 4;
    float4 v = *(const float4*)(x + base);
    fp16 h0,h1,h2,h3,l0,l1,l2,l3;
    split_fp16(v.x,h0,l0); split_fp16(v.y,h1,l1);
    split_fp16(v.z,h2,l2); split_fp16(v.w,h3,l3);
    __half2* ph = (__half2*)(g_xhi + base);
    __half2* pl = (__half2*)(g_xlo + base);
    ph[0] = __halves2half2(h0,h1); ph[1] = __halves2half2(h2,h3);
    pl[0] = __halves2half2(l0,l1); pl[1] = __halves2half2(l2,l3);
}

// ---------------------------------------------------------------------------
// Kernel B: transpose + convert: in[R,C] fp32 -> out [C,R] fp16 (single)
// ---------------------------------------------------------------------------
__global__ __launch_bounds__(256) void transpose_convert_kernel(
    const float* __restrict__ in, fp16* __restrict__ out, int R, int C)
{
    __shared__ float tile[32][33];
    int c0 = blockIdx.x * 32, r0 = blockIdx.y * 32;
    int tx = threadIdx.x, ty = threadIdx.y;
#pragma unroll
    for (int j = 0; j < 4; j++) {
        int r = r0 + ty + j*8;
        tile[ty + j*8][tx] = in[(size_t)r * C + c0 + tx];
    }
    __syncthreads();
#pragma unroll
    for (int j = 0; j < 4; j++) {
        int c = c0 + ty + j*8;
        int r = r0 + tx;
        out[(size_t)c * R + r] = __float2half_rn(tile[tx][ty + j*8]);
    }
}

// ---------------------------------------------------------------------------
// Kernel C: mma.sync fp16 GEMM (QKV + out-proj), A hi/lo split (2 MMAs/pair).
// CTA tile 128x128, K-chunk 32, 3-stage cp.async pipeline, 8 warps (2m x 4n).
// (unchanged from round 15)
// ---------------------------------------------------------------------------
#define KCHUNK 32
#define NIT (KK/KCHUNK)          // 32
#define ROWB 80                  // bytes per 32-elem fp16 row (64 data + 16 pad)
#define STG_A_HI 0
#define STG_A_LO 10240
#define STG_B    20480
#define STAGE_BYTES 30720
#define NSTAGE 3
#define GEMM_SMEM (NSTAGE*STAGE_BYTES)   // 92160

__global__ __launch_bounds__(256, 2) void gemm_kernel(
    int qkv_mode,
    const float* __restrict__ b0, const float* __restrict__ b1, const float* __restrict__ b2,
    float* __restrict__ oout)
{
    extern __shared__ char smem[];
    const uint32_t sb = smem_to_u32(smem);
    const int tid = threadIdx.x, wid = tid >> 5, lane = tid & 31;
    const int warp_m = wid >> 2, warp_n = wid & 3;
    const int M0 = blockIdx.x * 128;

    const fp16 *Ahi, *Alo, *Bw;
    const float* bias;
    size_t b_off; int b_stride;
    int h = 0, proj = 0, N0 = 0;

    if (qkv_mode) {
        int pn = blockIdx.y; proj = pn >> 3; h = pn & 7;
        Ahi = g_xhi; Alo = g_xlo;
        if (proj == 0)      { Bw = g_wtq; bias = b0; }
        else if (proj == 1) { Bw = g_wtk; bias = b1; }
        else                { Bw = g_wtv; bias = b2; }
        bias += h * EE;
        b_off = (size_t)h * DD; b_stride = HH * DD;   // Wt rows: stride 8192, +h*1024
    } else {
        N0 = blockIdx.y * 128;
        Ahi = g_attn_hi; Alo = g_attn_lo; Bw = g_wot;
        bias = b0 + N0;
        b_off = (size_t)N0 * DD; b_stride = DD;
    }

    float c[4][4][4];
#pragma unroll
    for (int mf = 0; mf < 4; mf++)
#pragma unroll
        for (int nf = 0; nf < 4; nf++)
#pragma unroll
            for (int k = 0; k < 4; k++) c[mf][nf][k] = 0.f;

    auto load_stage = [&](int st, int k0) {
        uint32_t base = sb + st * STAGE_BYTES;
#pragma unroll
        for (int r = 0; r < 2; r++) {
            int chunk = tid + r * 256;          // 0..511
            int row = chunk >> 2, cc = chunk & 3;
            uint32_t off = (uint32_t)(row * ROWB + cc * 16);
            size_t a_idx = (size_t)(M0 + row) * KK + k0 + cc * 8;
            size_t b_idx = b_off + (size_t)row * b_stride + k0 + cc * 8;
            cp_async16(base + STG_A_HI + off, Ahi + a_idx);
            cp_async16(base + STG_A_LO + off, Alo + a_idx);
            cp_async16(base + STG_B    + off, Bw  + b_idx);
        }
        asm volatile("cp.async.commit_group;\n" ::: "memory");
    };

    // Prologue: fill stages 0 and 1
    load_stage(0, 0);
    load_stage(1, KCHUNK);

    int stage = 0;
    for (int it = 0; it < NIT; ++it) {
        if (it + 2 < NIT) {
            int st2 = stage + 2; if (st2 >= NSTAGE) st2 -= NSTAGE;
            load_stage(st2, (it + 2) * KCHUNK);
            asm volatile("cp.async.wait_group 2;\n" ::: "memory");
        } else if (it + 1 < NIT) {
            asm volatile("cp.async.wait_group 1;\n" ::: "memory");
        } else {
            asm volatile("cp.async.wait_group 0;\n" ::: "memory");
        }
        __syncthreads();

        const uint32_t sA = sb + stage * STAGE_BYTES;
#pragma unroll
        for (int ks = 0; ks < 2; ks++) {
            uint32_t ah[4][4], al[4][4], bw[4][2];
            {
                int rowf = warp_m * 64 + (lane & 15);
                int ckA = ks * 2 + (lane >> 4);
#pragma unroll
                for (int mf = 0; mf < 4; mf++) {
                    uint32_t off = (uint32_t)((rowf + mf * 16) * ROWB + ckA * 16);
                    ldsm4(ah[mf], sA + STG_A_HI + off);
                    ldsm4(al[mf], sA + STG_A_LO + off);
                }
            }
            {
                int l = lane & 15;
                int rowb = warp_n * 32 + (l & 7);
                int ckB = ks * 2 + (l >> 3);
#pragma unroll
                for (int nf = 0; nf < 4; nf++) {
                    uint32_t off = (uint32_t)((rowb + nf * 8) * ROWB + ckB * 16);
                    ldsm2(bw[nf], sA + STG_B + off);
                }
            }
#pragma unroll
            for (int mf = 0; mf < 4; mf++)
#pragma unroll
                for (int nf = 0; nf < 4; nf++) {
                    mma16816(c[mf][nf], ah[mf], bw[nf]);
                    mma16816(c[mf][nf], al[mf], bw[nf]);
                }
        }
        __syncthreads();
        if (++stage >= NSTAGE) stage = 0;
    }

    const int g = lane >> 2, t4 = lane & 3;
#pragma unroll
    for (int mf = 0; mf < 4; mf++) {
#pragma unroll
        for (int half_ = 0; half_ < 2; half_++) {
            int row = M0 + warp_m * 64 + mf * 16 + g + half_ * 8;
            float* dst;
            if (qkv_mode) {
                int bidx = row >> 11, s = row & 2047;
                float* basep = (proj == 0) ? g_q : (proj == 1) ? g_k : g_v;
                dst = basep + (((size_t)(bidx * HH + h) * SS + s) * EE);
            } else {
                dst = oout + (size_t)row * DD + N0;
            }
#pragma unroll
            for (int nf = 0; nf < 4; nf++) {
                int col = warp_n * 32 + nf * 8 + t4 * 2;
                float2 v;
                v.x = c[mf][nf][half_ * 2 + 0] + bias[col];
                v.y = c[mf][nf][half_ * 2 + 1] + bias[col + 1];
                *(float2*)(dst + col) = v;
            }
        }
    }
}

// ---------------------------------------------------------------------------
// Kernel D: dilated local window attention, CHAINED: one warp per 4-query group
// (s, s+d, s+2d, s+3d). Window positions form one arithmetic sequence
// pos_t = P0 + d*t, t in [0, 18]; query i uses j = t - i. K/V traffic /3.37.
// Per-logit arithmetic identical to previous version (bit-exact).
// ---------------------------------------------------------------------------
#define GQ 4
__global__ __launch_bounds__(256) void attn_kernel(
    const float* __restrict__ bk, const float* __restrict__ bv,
    const int*   __restrict__ dil)
{
    const int gwarp = (blockIdx.x * blockDim.x + threadIdx.x) >> 5;
    const int lane  = threadIdx.x & 31;
    // 8192 warps: bh = gwarp/512, group g = gwarp%512
    const int bh = gwarp >> 9;
    const int gr = gwarp & 511;
    const int h  = bh & 7;
    const int b  = bh >> 3;

    const int d   = dil[h];                       // power of 2: 1,2,4,8
    const int ld2 = (d == 1) ? 0 : (d == 2) ? 1 : (d == 4) ? 2 : 3;
    const int r   = gr & (d - 1);                 // residue
    const int c4  = gr >> ld2;                    // chain group index
    const int off = (d * (KW - 1)) >> 1;
    const int P0  = r + ((c4 * GQ) << ld2) - off; // pos_t = P0 + d*t

    const size_t base = (size_t)bh * SS * EE;
    const float4 kb4 = *(const float4*)(bk + h*EE + lane*4);
    const float4 vb4 = *(const float4*)(bv + h*EE + lane*4);

    int sq[GQ];
    float4 q4[GQ];
#pragma unroll
    for (int i = 0; i < GQ; i++) {
        sq[i] = r + ((c4 * GQ + i) << ld2);
        q4[i] = *(const float4*)(g_q + base + (size_t)sq[i] * EE + lane*4);
    }

    float part[GQ][KW];
#pragma unroll
    for (int t = 0; t < GQ + KW - 1; t++) {
        int pos = P0 + (t << ld2);
        float4 k4 = (pos >= 0 && pos < SS)
                  ? *(const float4*)(g_k + base + (size_t)pos * EE + lane*4)
                  : kb4;
#pragma unroll
        for (int i = 0; i < GQ; i++) {
            int j = t - i;
            if (j >= 0 && j < KW) {
                part[i][j] = q4[i].x*k4.x + q4[i].y*k4.y + q4[i].z*k4.z + q4[i].w*k4.w;
            }
        }
    }

    // warp-reduce all logits (same shfl tree as before)
#pragma unroll
    for (int i = 0; i < GQ; i++)
#pragma unroll
        for (int j = 0; j < KW; j++) {
            float p = part[i][j];
            p += __shfl_xor_sync(0xFFFFFFFFu, p, 16);
            p += __shfl_xor_sync(0xFFFFFFFFu, p, 8);
            p += __shfl_xor_sync(0xFFFFFFFFu, p, 4);
            p += __shfl_xor_sync(0xFFFFFFFFu, p, 2);
            p += __shfl_xor_sync(0xFFFFFFFFu, p, 1);
            part[i][j] = p;
        }

    // softmax per query (identical order)
#pragma unroll
    for (int i = 0; i < GQ; i++) {
        float mx = part[i][0];
#pragma unroll
        for (int j = 1; j < KW; j++) mx = fmaxf(mx, part[i][j]);
        float sum = 0.f;
#pragma unroll
        for (int j = 0; j < KW; j++) { part[i][j] = expf(part[i][j] - mx); sum += part[i][j]; }
        float inv = 1.0f / sum;
#pragma unroll
        for (int j = 0; j < KW; j++) part[i][j] *= inv;
    }

    float4 acc[GQ];
#pragma unroll
    for (int i = 0; i < GQ; i++) acc[i] = make_float4(0.f, 0.f, 0.f, 0.f);

#pragma unroll
    for (int t = 0; t < GQ + KW - 1; t++) {
        int pos = P0 + (t << ld2);
        float4 v4 = (pos >= 0 && pos < SS)
                  ? *(const float4*)(g_v + base + (size_t)pos * EE + lane*4)
                  : vb4;
#pragma unroll
        for (int i = 0; i < GQ; i++) {
            int j = t - i;
            if (j >= 0 && j < KW) {
                float p = part[i][j];
                acc[i].x = fmaf(p, v4.x, acc[i].x);
                acc[i].y = fmaf(p, v4.y, acc[i].y);
                acc[i].z = fmaf(p, v4.z, acc[i].z);
                acc[i].w = fmaf(p, v4.w, acc[i].w);
            }
        }
    }

    const float sc = 0.08838834764831845f;   // 1/sqrt(128), AFTER softmax*V (faithful quirk)
#pragma unroll
    for (int i = 0; i < GQ; i++) {
        float4 a = acc[i];
        a.x *= sc; a.y *= sc; a.z *= sc; a.w *= sc;
        fp16 h0,h1,h2,h3,l0,l1,l2,l3;
        split_fp16(a.x,h0,l0); split_fp16(a.y,h1,l1);
        split_fp16(a.z,h2,l2); split_fp16(a.w,h3,l3);
        const size_t ob = (((size_t)(b*SS + sq[i]) * HH + h) * EE) + lane*4;
        __half2* ph = (__half2*)(g_attn_hi + ob);
        __half2* pl = (__half2*)(g_attn_lo + ob);
        ph[0] = __halves2half2(h0,h1); ph[1] = __halves2half2(h2,h3);
        pl[0] = __halves2half2(l0,l1); pl[1] = __halves2half2(l2,l3);
    }
}

// ---------------------------------------------------------------------------
extern "C" void kernel_launch(void* const* d_in, const int* in_sizes, int n_in,
                              void* d_out, int out_size)
{
    const float* x   = (const float*)d_in[0];
    const float* Wq  = (const float*)d_in[1];
    const float* bq  = (const float*)d_in[2];
    const float* Wk  = (const float*)d_in[3];
    const float* bk  = (const float*)d_in[4];
    const float* Wv  = (const float*)d_in[5];
    const float* bv  = (const float*)d_in[6];
    const float* Wo  = (const float*)d_in[7];
    const float* bo  = (const float*)d_in[8];
    const int*   dil = (const int*)d_in[9];
    float* out = (float*)d_out;

    cudaFuncSetAttribute(gemm_kernel, cudaFuncAttributeMaxDynamicSharedMemorySize, GEMM_SMEM);

    // 0) split-convert x
    convert_x_kernel<<<MM*KK/(256*4), 256>>>(x);

    // 1) transpose + convert weights (single fp16)
    {
        fp16 *wtq, *wtk, *wtv, *wot;
        cudaGetSymbolAddress((void**)&wtq, g_wtq);
        cudaGetSymbolAddress((void**)&wtk, g_wtk);
        cudaGetSymbolAddress((void**)&wtv, g_wtv);
        cudaGetSymbolAddress((void**)&wot, g_wot);
        dim3 blk(32, 8);
        transpose_convert_kernel<<<dim3(EE/32, HH*DD/32), blk>>>(Wq, wtq, HH*DD, EE);
        transpose_convert_kernel<<<dim3(EE/32, HH*DD/32), blk>>>(Wk, wtk, HH*DD, EE);
        transpose_convert_kernel<<<dim3(EE/32, HH*DD/32), blk>>>(Wv, wtv, HH*DD, EE);
        transpose_convert_kernel<<<dim3(DD/32, HH*EE/32), blk>>>(Wo, wot, HH*EE, DD);
    }

    // 2) QKV projections via mma.sync (grid: 32 m-tiles x 24 proj/head)
    gemm_kernel<<<dim3(MM/128, 24), 256, GEMM_SMEM>>>(1, bq, bk, bv, nullptr);

    // 3) windowed attention, chained: 8192 warps -> 1024 blocks x 256
    attn_kernel<<<(BB*HH*SS/GQ)/8, 256>>>(bk, bv, dil);

    // 4) output projection via mma.sync (grid: 32 m-tiles x 8 n-tiles)
    gemm_kernel<<<dim3(MM/128, DD/128), 256, GEMM_SMEM>>>(0, bo, nullptr, nullptr, out);
}

// round 17
// speedup vs baseline: 1.5625x; 1.5625x over previous
#include <cuda_runtime.h>
#include <cuda_fp16.h>
#include <cstdint>

// Problem constants
#define BB 2
#define SS 2048
#define DD 1024
#define HH 8
#define EE 128
#define KW 16
#define MM (BB*SS)          // 4096 rows
#define KK 1024             // GEMM K (both projections)

typedef __half fp16;

// ---------------------------------------------------------------------------
// Device scratch (allocation-free rule)
// ---------------------------------------------------------------------------
__device__ fp16  g_xhi[MM*KK], g_xlo[MM*KK];       // x split [4096,1024]
__device__ fp16  g_wtq[EE*HH*DD];                  // Wq^T [128 (e), 8192 (h*1024+d)]
__device__ fp16  g_wtk[EE*HH*DD];
__device__ fp16  g_wtv[EE*HH*DD];
__device__ fp16  g_wot[DD*HH*EE];                  // Wo^T [1024 (d), 1024 (he)]
__device__ float g_q[BB*HH*SS*EE];                 // [B,H,S,E]
__device__ float g_k[BB*HH*SS*EE];
__device__ float g_v[BB*HH*SS*EE];
__device__ fp16  g_attn_hi[MM*KK], g_attn_lo[MM*KK];  // [B,S,H,E] = [4096,1024]

// ---------------------------------------------------------------------------
// Helpers (sm_80-class PTX only — legal on compute_103)
// ---------------------------------------------------------------------------
__device__ __forceinline__ uint32_t smem_to_u32(const void* p) {
    uint32_t a;
    asm("{ .reg .u64 t; cvta.to.shared.u64 t, %1; cvt.u32.u64 %0, t; }" : "=r"(a) : "l"(p));
    return a;
}
__device__ __forceinline__ void cp_async16(uint32_t saddr, const void* gptr) {
    asm volatile("cp.async.cg.shared.global [%0], [%1], 16;\n" :: "r"(saddr), "l"(gptr));
}
__device__ __forceinline__ void ldsm4(uint32_t* r, uint32_t addr) {
    asm volatile("ldmatrix.sync.aligned.m8n8.x4.shared.b16 {%0,%1,%2,%3}, [%4];\n"
        : "=r"(r[0]), "=r"(r[1]), "=r"(r[2]), "=r"(r[3]) : "r"(addr));
}
__device__ __forceinline__ void ldsm2(uint32_t* r, uint32_t addr) {
    asm volatile("ldmatrix.sync.aligned.m8n8.x2.shared.b16 {%0,%1}, [%2];\n"
        : "=r"(r[0]), "=r"(r[1]) : "r"(addr));
}
__device__ __forceinline__ void mma16816(float* c, const uint32_t* a, const uint32_t* b) {
    asm volatile("mma.sync.aligned.m16n8k16.row.col.f32.f16.f16.f32 "
        "{%0,%1,%2,%3}, {%4,%5,%6,%7}, {%8,%9}, {%0,%1,%2,%3};\n"
        : "+f"(c[0]), "+f"(c[1]), "+f"(c[2]), "+f"(c[3])
        : "r"(a[0]), "r"(a[1]), "r"(a[2]), "r"(a[3]), "r"(b[0]), "r"(b[1]));
}

__device__ __forceinline__ void split_fp16(float v, fp16& hi, fp16& lo) {
    hi = __float2half_rn(v);
    lo = __float2half_rn(v - __half2float(hi));
}

// ---------------------------------------------------------------------------
// Kernel A: elementwise split-convert of x -> g_xhi/g_xlo (fp16)
// ---------------------------------------------------------------------------
__global__ __launch_bounds__(256) void convert_x_kernel(const float* __restrict__ x) {
    int t = blockIdx.x * 256 + threadIdx.x;
    size_t base = (size_t)t * 4;
    float4 v = *(const float4*)(x + base);
    fp16 h0,h1,h2,h3,l0,l1,l2,l3;
    split_fp16(v.x,h0,l0); split_fp16(v.y,h1,l1);
    split_fp16(v.z,h2,l2); split_fp16(v.w,h3,l3);
    __half2* ph = (__half2*)(g_xhi + base);
    __half2* pl = (__half2*)(g_xlo + base);
    ph[0] = __halves2half2(h0,h1); ph[1] = __halves2half2(h2,h3);
    pl[0] = __halves2half2(l0,l1); pl[1] = __halves2half2(l2,l3);
}

// ---------------------------------------------------------------------------
// Kernel B: transpose + convert: in[R,C] fp32 -> out [C,R] fp16 (single)
// ---------------------------------------------------------------------------
__global__ __launch_bounds__(256) void transpose_convert_kernel(
    const float* __restrict__ in, fp16* __restrict__ out, int R, int C)
{
    __shared__ float tile[32][33];
    int c0 = blockIdx.x * 32, r0 = blockIdx.y * 32;
    int tx = threadIdx.x, ty = threadIdx.y;
#pragma unroll
    for (int j = 0; j < 4; j++) {
        int r = r0 + ty + j*8;
        tile[ty + j*8][tx] = in[(size_t)r * C + c0 + tx];
    }
    __syncthreads();
#pragma unroll
    for (int j = 0; j < 4; j++) {
        int c = c0 + ty + j*8;
        int r = r0 + tx;
        out[(size_t)c * R + r] = __float2half_rn(tile[tx][ty + j*8]);
    }
}

// ---------------------------------------------------------------------------
// Kernel C: mma.sync fp16 GEMM (QKV + out-proj), A hi/lo split (2 MMAs/pair).
// CTA tile 128x128, K-chunk 32, 3-stage cp.async pipeline, 8 warps (2m x 4n).
// Single __syncthreads per iteration: loads issued post-sync target the
// buffer of iteration it-1, which all warps have finished reading.
// ---------------------------------------------------------------------------
#define KCHUNK 32
#define NIT (KK/KCHUNK)          // 32
#define ROWB 80                  // bytes per 32-elem fp16 row (64 data + 16 pad)
#define STG_A_HI 0
#define STG_A_LO 10240
#define STG_B    20480
#define STAGE_BYTES 30720
#define NSTAGE 3
#define GEMM_SMEM (NSTAGE*STAGE_BYTES)   // 92160

__global__ __launch_bounds__(256, 2) void gemm_kernel(
    int qkv_mode,
    const float* __restrict__ b0, const float* __restrict__ b1, const float* __restrict__ b2,
    float* __restrict__ oout)
{
    extern __shared__ char smem[];
    const uint32_t sb = smem_to_u32(smem);
    const int tid = threadIdx.x, wid = tid >> 5, lane = tid & 31;
    const int warp_m = wid >> 2, warp_n = wid & 3;
    const int M0 = blockIdx.x * 128;

    const fp16 *Ahi, *Alo, *Bw;
    const float* bias;
    size_t b_off; int b_stride;
    int h = 0, proj = 0, N0 = 0;

    if (qkv_mode) {
        int pn = blockIdx.y; proj = pn >> 3; h = pn & 7;
        Ahi = g_xhi; Alo = g_xlo;
        if (proj == 0)      { Bw = g_wtq; bias = b0; }
        else if (proj == 1) { Bw = g_wtk; bias = b1; }
        else                { Bw = g_wtv; bias = b2; }
        bias += h * EE;
        b_off = (size_t)h * DD; b_stride = HH * DD;   // Wt rows: stride 8192, +h*1024
    } else {
        N0 = blockIdx.y * 128;
        Ahi = g_attn_hi; Alo = g_attn_lo; Bw = g_wot;
        bias = b0 + N0;
        b_off = (size_t)N0 * DD; b_stride = DD;
    }

    float c[4][4][4];
#pragma unroll
    for (int mf = 0; mf < 4; mf++)
#pragma unroll
        for (int nf = 0; nf < 4; nf++)
#pragma unroll
            for (int k = 0; k < 4; k++) c[mf][nf][k] = 0.f;

    auto load_stage = [&](int st, int k0) {
        uint32_t base = sb + st * STAGE_BYTES;
#pragma unroll
        for (int r = 0; r < 2; r++) {
            int chunk = tid + r * 256;          // 0..511
            int row = chunk >> 2, cc = chunk & 3;
            uint32_t off = (uint32_t)(row * ROWB + cc * 16);
            size_t a_idx = (size_t)(M0 + row) * KK + k0 + cc * 8;
            size_t b_idx = b_off + (size_t)row * b_stride + k0 + cc * 8;
            cp_async16(base + STG_A_HI + off, Ahi + a_idx);
            cp_async16(base + STG_A_LO + off, Alo + a_idx);
            cp_async16(base + STG_B    + off, Bw  + b_idx);
        }
        asm volatile("cp.async.commit_group;\n" ::: "memory");
    };

    // Prologue: fill stages 0 and 1
    load_stage(0, 0);
    load_stage(1, KCHUNK);

    int stage = 0;
    for (int it = 0; it < NIT; ++it) {
        // Wait until stage `it` has landed (leave the next group in flight).
        if (it + 1 < NIT) {
            asm volatile("cp.async.wait_group 1;\n" ::: "memory");
        } else {
            asm volatile("cp.async.wait_group 0;\n" ::: "memory");
        }
        __syncthreads();
        // All warps finished reading stage (it-1) == (stage+2)%NSTAGE: safe to refill.
        if (it + 2 < NIT) {
            int st2 = stage + 2; if (st2 >= NSTAGE) st2 -= NSTAGE;
            load_stage(st2, (it + 2) * KCHUNK);
        }

        const uint32_t sA = sb + stage * STAGE_BYTES;
#pragma unroll
        for (int ks = 0; ks < 2; ks++) {
            uint32_t ah[4][4], al[4][4], bw[4][2];
            {
                int rowf = warp_m * 64 + (lane & 15);
                int ckA = ks * 2 + (lane >> 4);
#pragma unroll
                for (int mf = 0; mf < 4; mf++) {
                    uint32_t off = (uint32_t)((rowf + mf * 16) * ROWB + ckA * 16);
                    ldsm4(ah[mf], sA + STG_A_HI + off);
                    ldsm4(al[mf], sA + STG_A_LO + off);
                }
            }
            {
                int l = lane & 15;
                int rowb = warp_n * 32 + (l & 7);
                int ckB = ks * 2 + (l >> 3);
#pragma unroll
                for (int nf = 0; nf < 4; nf++) {
                    uint32_t off = (uint32_t)((rowb + nf * 8) * ROWB + ckB * 16);
                    ldsm2(bw[nf], sA + STG_B + off);
                }
            }
#pragma unroll
            for (int mf = 0; mf < 4; mf++)
#pragma unroll
                for (int nf = 0; nf < 4; nf++) {
                    mma16816(c[mf][nf], ah[mf], bw[nf]);
                    mma16816(c[mf][nf], al[mf], bw[nf]);
                }
        }
        if (++stage >= NSTAGE) stage = 0;
    }

    // Epilogue: c0,c1 -> row g cols 2t,2t+1 ; c2,c3 -> row g+8
    const int g = lane >> 2, t4 = lane & 3;
#pragma unroll
    for (int mf = 0; mf < 4; mf++) {
#pragma unroll
        for (int half_ = 0; half_ < 2; half_++) {
            int row = M0 + warp_m * 64 + mf * 16 + g + half_ * 8;
            float* dst;
            if (qkv_mode) {
                int bidx = row >> 11, s = row & 2047;
                float* basep = (proj == 0) ? g_q : (proj == 1) ? g_k : g_v;
                dst = basep + (((size_t)(bidx * HH + h) * SS + s) * EE);
            } else {
                dst = oout + (size_t)row * DD + N0;
            }
#pragma unroll
            for (int nf = 0; nf < 4; nf++) {
                int col = warp_n * 32 + nf * 8 + t4 * 2;
                float2 v;
                v.x = c[mf][nf][half_ * 2 + 0] + bias[col];
                v.y = c[mf][nf][half_ * 2 + 1] + bias[col + 1];
                *(float2*)(dst + col) = v;
            }
        }
    }
}

// ---------------------------------------------------------------------------
// Kernel D: dilated local window attention. One warp per (b,h,s).
// (exact round-15 version — measured good)
// ---------------------------------------------------------------------------
__global__ __launch_bounds__(256) void attn_kernel(
    const float* __restrict__ bk, const float* __restrict__ bv,
    const int*   __restrict__ dil)
{
    const int gwarp = (blockIdx.x * blockDim.x + threadIdx.x) >> 5;
    const int lane  = threadIdx.x & 31;
    if (gwarp >= BB*HH*SS) return;

    const int s  = gwarp & (SS - 1);
    const int bh = gwarp >> 11;
    const int h  = bh & 7;
    const int b  = bh >> 3;

    const int d   = dil[h];
    const int off = (d * (KW - 1)) >> 1;

    const size_t base = (size_t)bh * SS * EE;
    const float4 q4  = *(const float4*)(g_q + base + (size_t)s * EE + lane*4);
    const float4 kb4 = *(const float4*)(bk + h*EE + lane*4);
    const float4 vb4 = *(const float4*)(bv + h*EE + lane*4);

    float logits[KW];
#pragma unroll
    for (int j = 0; j < KW; j++) {
        int pos = s + d*j - off;
        float4 k4 = (pos >= 0 && pos < SS)
                  ? *(const float4*)(g_k + base + (size_t)pos * EE + lane*4)
                  : kb4;
        float p = q4.x*k4.x + q4.y*k4.y + q4.z*k4.z + q4.w*k4.w;
        p += __shfl_xor_sync(0xFFFFFFFFu, p, 16);
        p += __shfl_xor_sync(0xFFFFFFFFu, p, 8);
        p += __shfl_xor_sync(0xFFFFFFFFu, p, 4);
        p += __shfl_xor_sync(0xFFFFFFFFu, p, 2);
        p += __shfl_xor_sync(0xFFFFFFFFu, p, 1);
        logits[j] = p;
    }

    float mx = logits[0];
#pragma unroll
    for (int j = 1; j < KW; j++) mx = fmaxf(mx, logits[j]);
    float sum = 0.f;
#pragma unroll
    for (int j = 0; j < KW; j++) { logits[j] = expf(logits[j] - mx); sum += logits[j]; }
    const float inv = 1.0f / sum;

    float4 acc = make_float4(0.f, 0.f, 0.f, 0.f);
#pragma unroll
    for (int j = 0; j < KW; j++) {
        int pos = s + d*j - off;
        float4 v4 = (pos >= 0 && pos < SS)
                  ? *(const float4*)(g_v + base + (size_t)pos * EE + lane*4)
                  : vb4;
        float p = logits[j] * inv;
        acc.x = fmaf(p, v4.x, acc.x);
        acc.y = fmaf(p, v4.y, acc.y);
        acc.z = fmaf(p, v4.z, acc.z);
        acc.w = fmaf(p, v4.w, acc.w);
    }
    const float sc = 0.08838834764831845f;   // 1/sqrt(128), AFTER softmax*V (faithful quirk)
    acc.x *= sc; acc.y *= sc; acc.z *= sc; acc.w *= sc;

    fp16 h0,h1,h2,h3,l0,l1,l2,l3;
    split_fp16(acc.x,h0,l0); split_fp16(acc.y,h1,l1);
    split_fp16(acc.z,h2,l2); split_fp16(acc.w,h3,l3);
    const size_t ob = (((size_t)(b*SS + s) * HH + h) * EE) + lane*4;
    __half2* ph = (__half2*)(g_attn_hi + ob);
    __half2* pl = (__half2*)(g_attn_lo + ob);
    ph[0] = __halves2half2(h0,h1); ph[1] = __halves2half2(h2,h3);
    pl[0] = __halves2half2(l0,l1); pl[1] = __halves2half2(l2,l3);
}

// ---------------------------------------------------------------------------
extern "C" void kernel_launch(void* const* d_in, const int* in_sizes, int n_in,
                              void* d_out, int out_size)
{
    const float* x   = (const float*)d_in[0];
    const float* Wq  = (const float*)d_in[1];
    const float* bq  = (const float*)d_in[2];
    const float* Wk  = (const float*)d_in[3];
    const float* bk  = (const float*)d_in[4];
    const float* Wv  = (const float*)d_in[5];
    const float* bv  = (const float*)d_in[6];
    const float* Wo  = (const float*)d_in[7];
    const float* bo  = (const float*)d_in[8];
    const int*   dil = (const int*)d_in[9];
    float* out = (float*)d_out;

    cudaFuncSetAttribute(gemm_kernel, cudaFuncAttributeMaxDynamicSharedMemorySize, GEMM_SMEM);

    // 0) split-convert x
    convert_x_kernel<<<MM*KK/(256*4), 256>>>(x);

    // 1) transpose + convert weights (single fp16)
    {
        fp16 *wtq, *wtk, *wtv, *wot;
        cudaGetSymbolAddress((void**)&wtq, g_wtq);
        cudaGetSymbolAddress((void**)&wtk, g_wtk);
        cudaGetSymbolAddress((void**)&wtv, g_wtv);
        cudaGetSymbolAddress((void**)&wot, g_wot);
        dim3 blk(32, 8);
        transpose_convert_kernel<<<dim3(EE/32, HH*DD/32), blk>>>(Wq, wtq, HH*DD, EE);
        transpose_convert_kernel<<<dim3(EE/32, HH*DD/32), blk>>>(Wk, wtk, HH*DD, EE);
        transpose_convert_kernel<<<dim3(EE/32, HH*DD/32), blk>>>(Wv, wtv, HH*DD, EE);
        transpose_convert_kernel<<<dim3(DD/32, HH*EE/32), blk>>>(Wo, wot, HH*EE, DD);
    }

    // 2) QKV projections via mma.sync (grid: 32 m-tiles x 24 proj/head)
    gemm_kernel<<<dim3(MM/128, 24), 256, GEMM_SMEM>>>(1, bq, bk, bv, nullptr);

    // 3) windowed attention (one warp per (b,h,s))
    attn_kernel<<<(BB*HH*SS)/8, 256>>>(bk, bv, dil);

    // 4) output projection via mma.sync (grid: 32 m-tiles x 8 n-tiles)
    gemm_kernel<<<dim3(MM/128, DD/128), 256, GEMM_SMEM>>>(0, bo, nullptr, nullptr, out);
}